// round 9
// baseline (speedup 1.0000x reference)
#include <cuda_runtime.h>
#include <cuda_bf16.h>
#include <math.h>

// Problem constants
#define Bb  2
#define Tt  2048
#define Ee  2048
#define Hh  32
#define KVh 8
#define Dd  64
#define Mrows (Bb*Tt)          // 4096
#define QN  (Hh*Dd)            // 2048
#define KN  (KVh*Dd)           // 512

// Scratch (device globals — no allocations allowed)
__device__ float g_Q[(size_t)Mrows*QN];
__device__ float g_K[(size_t)Mrows*KN];
__device__ float g_V[(size_t)Mrows*KN];
__device__ float g_O[(size_t)Mrows*QN];

// ---------------------------------------------------------------------------
// SGEMM: C[M,N] = A[M,K] * B[K,N], row-major, fp32.
// 128x128 block tile, BK=16, 256 threads, 8x8 per-thread microtile.
// Requires M%128==0, N%128==0, K%16==0 (true for all our shapes).
// ---------------------------------------------------------------------------
#define GBM 128
#define GBN 128
#define GBK 16

__global__ void __launch_bounds__(256) sgemm_kernel(
    const float* __restrict__ A, const float* __restrict__ B,
    float* __restrict__ C, int M, int N, int K)
{
    __shared__ float As[GBK][GBM];   // transposed: As[k][m]
    __shared__ float Bs[GBK][GBN];

    const int tid = threadIdx.x;
    const int tx  = tid & 15;        // 0..15 (N direction)
    const int ty  = tid >> 4;        // 0..15 (M direction)

    const float* Ab = A + (size_t)blockIdx.y * GBM * K;
    const float* Bb2 = B + (size_t)blockIdx.x * GBN;

    float acc[8][8];
#pragma unroll
    for (int i = 0; i < 8; i++)
#pragma unroll
        for (int j = 0; j < 8; j++) acc[i][j] = 0.0f;

    for (int kt = 0; kt < K; kt += GBK) {
        // Load A tile: 128 rows x 16 k  -> 512 float4, 2 per thread
#pragma unroll
        for (int it = 0; it < 2; it++) {
            int f  = tid + it * 256;
            int r  = f >> 2;
            int kc = (f & 3) << 2;
            float4 av = *(const float4*)(Ab + (size_t)r * K + kt + kc);
            As[kc + 0][r] = av.x;
            As[kc + 1][r] = av.y;
            As[kc + 2][r] = av.z;
            As[kc + 3][r] = av.w;
            // Load B tile: 16 rows x 128 n -> 512 float4, 2 per thread
            int br  = f >> 5;
            int bnc = (f & 31) << 2;
            *(float4*)(&Bs[br][bnc]) =
                *(const float4*)(Bb2 + (size_t)(kt + br) * N + bnc);
        }
        __syncthreads();

#pragma unroll
        for (int k = 0; k < GBK; k++) {
            float ar[8], br[8];
            *(float4*)(ar)     = *(const float4*)(&As[k][ty * 8]);
            *(float4*)(ar + 4) = *(const float4*)(&As[k][ty * 8 + 4]);
            *(float4*)(br)     = *(const float4*)(&Bs[k][tx * 8]);
            *(float4*)(br + 4) = *(const float4*)(&Bs[k][tx * 8 + 4]);
#pragma unroll
            for (int i = 0; i < 8; i++)
#pragma unroll
                for (int j = 0; j < 8; j++)
                    acc[i][j] += ar[i] * br[j];
        }
        __syncthreads();
    }

    float* Cb = C + (size_t)(blockIdx.y * GBM + ty * 8) * N
                  + blockIdx.x * GBN + tx * 8;
#pragma unroll
    for (int i = 0; i < 8; i++) {
        *(float4*)(Cb + (size_t)i * N) =
            make_float4(acc[i][0], acc[i][1], acc[i][2], acc[i][3]);
        *(float4*)(Cb + (size_t)i * N + 4) =
            make_float4(acc[i][4], acc[i][5], acc[i][6], acc[i][7]);
    }
}

// ---------------------------------------------------------------------------
// RoPE: X[4096, nH*64] in place. pair j in 0..31 per head.
// freq layout: [T][32][2] (cos, sin)
// ---------------------------------------------------------------------------
__global__ void rope_kernel(float* __restrict__ X, const float* __restrict__ freq,
                            int nH, int total)
{
    int idx = blockIdx.x * blockDim.x + threadIdx.x;
    if (idx >= total) return;
    int j = idx & 31;
    int h = (idx >> 5) % nH;
    int m = idx / (32 * nH);
    int t = m & (Tt - 1);
    float c = freq[t * 64 + j * 2 + 0];
    float s = freq[t * 64 + j * 2 + 1];
    float2* p = (float2*)(X + (size_t)m * nH * 64 + h * 64 + j * 2);
    float2 ab = *p;
    float2 o;
    o.x = ab.x * c - ab.y * s;
    o.y = ab.x * s + ab.y * c;
    *p = o;
}

// ---------------------------------------------------------------------------
// Causal flash attention, GQA (kv head = h/4), fp32.
// Grid: (T/64, H, B). 256 threads. 64 queries per CTA.
// Thread (ty,tx): rows ty*4..+3, cols tx*4..+3 (for both S and O tiles).
// smem: Qs[64][68] | Ks[64][68] (reused for P) | Vs[64][68]
// ---------------------------------------------------------------------------
#define APAD 68
#define ASM_BYTES (3 * 64 * APAD * 4)

__global__ void __launch_bounds__(256) attn_kernel()
{
    extern __shared__ float sm[];
    float* Qs = sm;
    float* Ks = sm + 64 * APAD;   // reused as P after softmax
    float* Vs = sm + 2 * 64 * APAD;

    const int qt = blockIdx.x;        // query tile
    const int h  = blockIdx.y;
    const int b  = blockIdx.z;
    const int kvh = h >> 2;           // R = 4

    const int tid = threadIdx.x;
    const int tx  = tid & 15;
    const int ty  = tid >> 4;
    const int r0  = ty * 4;
    const int c0  = tx * 4;

    const size_t qbase = ((size_t)b * Tt + (size_t)qt * 64) * QN + h * Dd;

    // Load Q tile (64 x 64): 1024 float4, 4 per thread
#pragma unroll
    for (int it = 0; it < 4; it++) {
        int f = tid + it * 256;
        int row = f >> 4, c4 = (f & 15) << 2;
        *(float4*)(&Qs[row * APAD + c4]) =
            *(const float4*)(&g_Q[qbase + (size_t)row * QN + c4]);
    }

    float O[4][4];
    float mrow[4], lrow[4];
#pragma unroll
    for (int i = 0; i < 4; i++) {
        mrow[i] = -1e30f; lrow[i] = 0.0f;
#pragma unroll
        for (int j = 0; j < 4; j++) O[i][j] = 0.0f;
    }

    const float scale = 0.125f;   // 1/sqrt(64)

    for (int kt = 0; kt <= qt; kt++) {
        __syncthreads();   // protect Ks/Vs from previous iteration readers
        // Load K and V tiles (each 64 rows x 64 d)
        const size_t kbase = ((size_t)b * Tt + (size_t)kt * 64) * KN + kvh * Dd;
#pragma unroll
        for (int it = 0; it < 4; it++) {
            int f = tid + it * 256;
            int row = f >> 4, c4 = (f & 15) << 2;
            *(float4*)(&Ks[row * APAD + c4]) =
                *(const float4*)(&g_K[kbase + (size_t)row * KN + c4]);
            *(float4*)(&Vs[row * APAD + c4]) =
                *(const float4*)(&g_V[kbase + (size_t)row * KN + c4]);
        }
        __syncthreads();

        // S = Q K^T * scale, 4x4 microtile
        float s[4][4];
#pragma unroll
        for (int i = 0; i < 4; i++)
#pragma unroll
            for (int j = 0; j < 4; j++) s[i][j] = 0.0f;

#pragma unroll
        for (int d = 0; d < 64; d += 4) {
            float q[4][4], k[4][4];
#pragma unroll
            for (int i = 0; i < 4; i++)
                *(float4*)(q[i]) = *(const float4*)(&Qs[(r0 + i) * APAD + d]);
#pragma unroll
            for (int j = 0; j < 4; j++)
                *(float4*)(k[j]) = *(const float4*)(&Ks[(c0 + j) * APAD + d]);
#pragma unroll
            for (int i = 0; i < 4; i++)
#pragma unroll
                for (int j = 0; j < 4; j++) {
                    s[i][j] += q[i][0] * k[j][0];
                    s[i][j] += q[i][1] * k[j][1];
                    s[i][j] += q[i][2] * k[j][2];
                    s[i][j] += q[i][3] * k[j][3];
                }
        }

        // scale + causal mask (only needed on diagonal tile)
        if (kt == qt) {
#pragma unroll
            for (int i = 0; i < 4; i++) {
                int qg = r0 + i;
#pragma unroll
                for (int j = 0; j < 4; j++) {
                    int kg = c0 + j;
                    s[i][j] = (kg > qg) ? -1e30f : s[i][j] * scale;
                }
            }
        } else {
#pragma unroll
            for (int i = 0; i < 4; i++)
#pragma unroll
                for (int j = 0; j < 4; j++) s[i][j] *= scale;
        }

        // Online softmax (per-row state replicated across the 16 tx lanes)
#pragma unroll
        for (int i = 0; i < 4; i++) {
            float rmax = fmaxf(fmaxf(s[i][0], s[i][1]), fmaxf(s[i][2], s[i][3]));
#pragma unroll
            for (int msk = 8; msk >= 1; msk >>= 1)
                rmax = fmaxf(rmax, __shfl_xor_sync(0xffffffffu, rmax, msk));
            float mn = fmaxf(mrow[i], rmax);
            float alpha = __expf(mrow[i] - mn);
            mrow[i] = mn;
            float rsum = 0.0f;
#pragma unroll
            for (int j = 0; j < 4; j++) {
                float p = __expf(s[i][j] - mn);
                s[i][j] = p;
                rsum += p;
            }
#pragma unroll
            for (int msk = 8; msk >= 1; msk >>= 1)
                rsum += __shfl_xor_sync(0xffffffffu, rsum, msk);
            lrow[i] = lrow[i] * alpha + rsum;
#pragma unroll
            for (int j = 0; j < 4; j++) O[i][j] *= alpha;
        }

        __syncthreads();   // everyone finished reading Ks
        // Write P into Ks buffer: P[r][c]
#pragma unroll
        for (int i = 0; i < 4; i++)
            *(float4*)(&Ks[(r0 + i) * APAD + c0]) =
                make_float4(s[i][0], s[i][1], s[i][2], s[i][3]);
        __syncthreads();

        // O += P @ V  (rows r0.., cols of D = c0..)
#pragma unroll
        for (int k = 0; k < 64; k += 4) {
            float p[4][4];
#pragma unroll
            for (int i = 0; i < 4; i++)
                *(float4*)(p[i]) = *(const float4*)(&Ks[(r0 + i) * APAD + k]);
#pragma unroll
            for (int kk = 0; kk < 4; kk++) {
                float4 v = *(const float4*)(&Vs[(k + kk) * APAD + c0]);
#pragma unroll
                for (int i = 0; i < 4; i++) {
                    O[i][0] += p[i][kk] * v.x;
                    O[i][1] += p[i][kk] * v.y;
                    O[i][2] += p[i][kk] * v.z;
                    O[i][3] += p[i][kk] * v.w;
                }
            }
        }
    }

    // Normalize and write out
#pragma unroll
    for (int i = 0; i < 4; i++) {
        float inv = 1.0f / lrow[i];
        float4 o = make_float4(O[i][0] * inv, O[i][1] * inv,
                               O[i][2] * inv, O[i][3] * inv);
        *(float4*)(&g_O[qbase + (size_t)(r0 + i) * QN + c0]) = o;
    }
}

// ---------------------------------------------------------------------------
extern "C" void kernel_launch(void* const* d_in, const int* in_sizes, int n_in,
                              void* d_out, int out_size)
{
    const float* x    = (const float*)d_in[0];
    const float* freq = (const float*)d_in[1];
    const float* Wq   = (const float*)d_in[2];
    const float* Wk   = (const float*)d_in[3];
    const float* Wv   = (const float*)d_in[4];
    const float* Wo   = (const float*)d_in[5];
    float* out = (float*)d_out;

    void *pQ, *pK, *pV, *pO;
    cudaGetSymbolAddress(&pQ, g_Q);
    cudaGetSymbolAddress(&pK, g_K);
    cudaGetSymbolAddress(&pV, g_V);
    cudaGetSymbolAddress(&pO, g_O);

    cudaFuncSetAttribute(attn_kernel,
                         cudaFuncAttributeMaxDynamicSharedMemorySize, ASM_BYTES);

    // QKV projections
    sgemm_kernel<<<dim3(QN / GBN, Mrows / GBM), 256>>>(x, Wq, (float*)pQ,
                                                       Mrows, QN, Ee);
    sgemm_kernel<<<dim3(KN / GBN, Mrows / GBM), 256>>>(x, Wk, (float*)pK,
                                                       Mrows, KN, Ee);
    sgemm_kernel<<<dim3(KN / GBN, Mrows / GBM), 256>>>(x, Wv, (float*)pV,
                                                       Mrows, KN, Ee);

    // RoPE
    {
        int totQ = Mrows * Hh * 32;
        rope_kernel<<<(totQ + 255) / 256, 256>>>((float*)pQ, freq, Hh, totQ);
        int totK = Mrows * KVh * 32;
        rope_kernel<<<(totK + 255) / 256, 256>>>((float*)pK, freq, KVh, totK);
    }

    // Attention
    attn_kernel<<<dim3(Tt / 64, Hh, Bb), 256, ASM_BYTES>>>();

    // Output projection
    sgemm_kernel<<<dim3(Ee / GBN, Mrows / GBM), 256>>>((const float*)pO, Wo, out,
                                                       Mrows, Ee, QN);
}

// round 11
// speedup vs baseline: 1.1644x; 1.1644x over previous
#include <cuda_runtime.h>
#include <cuda_bf16.h>
#include <math.h>
#include <stdint.h>

// Problem constants
#define Bb  2
#define Tt  2048
#define Ee  2048
#define Hh  32
#define KVh 8
#define Dd  64
#define Mrows (Bb*Tt)          // 4096
#define QN  (Hh*Dd)            // 2048
#define KN  (KVh*Dd)           // 512

// Scratch (device globals — no allocations allowed)
__device__ float g_Q[(size_t)Mrows*QN];
__device__ float g_K[(size_t)Mrows*KN];
__device__ float g_V[(size_t)Mrows*KN];
__device__ float g_O[(size_t)Mrows*QN];

// ===========================================================================
// 3xTF32 tensor-core GEMM: C[M,N] = A[M,K] * B[K,N], row-major fp32 in/out.
// Split-precision: a = a_hi + a_lo (tf32 each); acc += ahi*bhi + alo*bhi
// + ahi*blo  ->  fp32-class accuracy on tensor cores.
// 128x128 CTA tile, BK=32, 256 threads = 8 warps (2x4), warp tile 64x32.
// A smem: lda=32 floats, XOR-swizzled -> conflict-free cp.async + ldmatrix.x4.
// B smem: ldb=136 floats (pad 8) -> conflict-free stores and LDS.32 reads.
// Double-buffered cp.async pipeline.
// ===========================================================================
#define BM 128
#define BN 128
#define BK 32
#define LDA 32
#define LDB 136
#define A_TILE_F (BM*LDA)                 // 4096 floats
#define B_TILE_F (BK*LDB)                 // 4352 floats
#define GEMM_SMEM_BYTES ((2*(A_TILE_F + B_TILE_F))*4)   // 67584 B

__device__ __forceinline__ void cp_async16(uint32_t dst, const void* src) {
    asm volatile("cp.async.cg.shared.global [%0], [%1], 16;\n"
                 :: "r"(dst), "l"(src));
}
__device__ __forceinline__ void cp_commit() {
    asm volatile("cp.async.commit_group;\n");
}
__device__ __forceinline__ void cp_wait1() {
    asm volatile("cp.async.wait_group 1;\n");
}
__device__ __forceinline__ void cp_wait0() {
    asm volatile("cp.async.wait_group 0;\n");
}
__device__ __forceinline__ void ldsm4(uint32_t a[4], uint32_t saddr) {
    asm volatile("ldmatrix.sync.aligned.m8n8.x4.shared.b16 {%0,%1,%2,%3}, [%4];\n"
                 : "=r"(a[0]), "=r"(a[1]), "=r"(a[2]), "=r"(a[3])
                 : "r"(saddr));
}
__device__ __forceinline__ uint32_t f2tf32(float x) {
    uint32_t r;
    asm("cvt.rna.tf32.f32 %0, %1;\n" : "=r"(r) : "f"(x));
    return r;
}
__device__ __forceinline__ void mma_tf32(float c[4], const uint32_t a[4],
                                         const uint32_t b[2]) {
    asm volatile(
        "mma.sync.aligned.m16n8k8.row.col.f32.tf32.tf32.f32 "
        "{%0,%1,%2,%3},{%4,%5,%6,%7},{%8,%9},{%0,%1,%2,%3};\n"
        : "+f"(c[0]), "+f"(c[1]), "+f"(c[2]), "+f"(c[3])
        : "r"(a[0]), "r"(a[1]), "r"(a[2]), "r"(a[3]), "r"(b[0]), "r"(b[1]));
}

__global__ void __launch_bounds__(256) gemm_tf32_kernel(
    const float* __restrict__ A, const float* __restrict__ B,
    float* __restrict__ C, int M, int N, int K)
{
    extern __shared__ float sm[];
    const int tid = threadIdx.x;
    const int bm = blockIdx.y, bn = blockIdx.x;

    float* AsBase = sm;                       // [2][A_TILE_F]
    float* BsBase = sm + 2 * A_TILE_F;        // [2][B_TILE_F]
    const uint32_t sA = (uint32_t)__cvta_generic_to_shared(AsBase);
    const uint32_t sB = (uint32_t)__cvta_generic_to_shared(BsBase);

    const float* Ag = A + (size_t)bm * BM * K;
    const float* Bg = B + (size_t)bn * BN;
    const int NT = K / BK;

    auto stage = [&](int kt, int buf) {
        uint32_t dA = sA + (uint32_t)buf * (A_TILE_F * 4);
        uint32_t dB = sB + (uint32_t)buf * (B_TILE_F * 4);
#pragma unroll
        for (int it = 0; it < 4; it++) {
            int f = it * 256 + tid;
            int r  = f >> 3, ch = f & 7;
            int chs = ch ^ (r & 7);
            cp_async16(dA + (uint32_t)(r * LDA + chs * 4) * 4,
                       Ag + (size_t)r * K + (size_t)kt * BK + ch * 4);
            int rb = f >> 5, c4 = f & 31;
            cp_async16(dB + (uint32_t)(rb * LDB + c4 * 4) * 4,
                       Bg + (size_t)(kt * BK + rb) * N + c4 * 4);
        }
    };

    stage(0, 0);
    cp_commit();

    const int warp = tid >> 5, lane = tid & 31;
    const int wm = (warp >> 2) * 64;     // warp M offset (0 or 64)
    const int wn = (warp & 3) * 32;      // warp N offset (0..96)

    float acc[4][4][4];
#pragma unroll
    for (int i = 0; i < 4; i++)
#pragma unroll
        for (int j = 0; j < 4; j++)
#pragma unroll
            for (int c = 0; c < 4; c++) acc[i][j][c] = 0.0f;

    for (int kt = 0; kt < NT; kt++) {
        const int buf = kt & 1;
        if (kt + 1 < NT) {
            stage(kt + 1, buf ^ 1);
            cp_commit();
            cp_wait1();
        } else {
            cp_wait0();
        }
        __syncthreads();

        const float* Bs = BsBase + buf * B_TILE_F;
        const uint32_t sAbuf = sA + (uint32_t)buf * (A_TILE_F * 4);

#pragma unroll
        for (int ks = 0; ks < 4; ks++) {
            // B fragments (LDS.32, padded, conflict-free), split hi/lo
            uint32_t bhi[4][2], blo[4][2];
            {
                const int r0 = ks * 8 + (lane & 3);
                const int cb = wn + (lane >> 2);
#pragma unroll
                for (int nj = 0; nj < 4; nj++) {
                    float b0 = Bs[r0 * LDB + cb + nj * 8];
                    float b1 = Bs[(r0 + 4) * LDB + cb + nj * 8];
                    bhi[nj][0] = f2tf32(b0);
                    bhi[nj][1] = f2tf32(b1);
                    blo[nj][0] = f2tf32(b0 - __uint_as_float(bhi[nj][0]));
                    blo[nj][1] = f2tf32(b1 - __uint_as_float(bhi[nj][1]));
                }
            }
#pragma unroll
            for (int mi = 0; mi < 4; mi++) {
                // A fragment via ldmatrix.x4 (swizzled), split hi/lo
                uint32_t araw[4], ahi[4], alo[4];
                {
                    int row = wm + mi * 16 + (lane & 15);
                    int ch  = ks * 2 + (lane >> 4);
                    int chs = ch ^ (row & 7);
                    ldsm4(araw, sAbuf + (uint32_t)(row * LDA + chs * 4) * 4);
                }
#pragma unroll
                for (int t = 0; t < 4; t++) {
                    float a = __uint_as_float(araw[t]);
                    ahi[t] = f2tf32(a);
                    alo[t] = f2tf32(a - __uint_as_float(ahi[t]));
                }
#pragma unroll
                for (int nj = 0; nj < 4; nj++) {
                    mma_tf32(acc[mi][nj], alo, bhi[nj]);   // correction terms
                    mma_tf32(acc[mi][nj], ahi, blo[nj]);   // first (smaller)
                    mma_tf32(acc[mi][nj], ahi, bhi[nj]);   // main term
                }
            }
        }
        __syncthreads();
    }

    // Epilogue: c0,c1 at (row, 2t..2t+1), c2,c3 at (row+8, ...)
    const int g = lane >> 2, t = lane & 3;
#pragma unroll
    for (int mi = 0; mi < 4; mi++) {
        size_t row = (size_t)bm * BM + wm + mi * 16 + g;
#pragma unroll
        for (int nj = 0; nj < 4; nj++) {
            int col = bn * BN + wn + nj * 8 + t * 2;
            *(float2*)(C + row * N + col) =
                make_float2(acc[mi][nj][0], acc[mi][nj][1]);
            *(float2*)(C + (row + 8) * N + col) =
                make_float2(acc[mi][nj][2], acc[mi][nj][3]);
        }
    }
}

// ---------------------------------------------------------------------------
// RoPE: X[4096, nH*64] in place. pair j in 0..31 per head.
// ---------------------------------------------------------------------------
__global__ void rope_kernel(float* __restrict__ X, const float* __restrict__ freq,
                            int nH, int total)
{
    int idx = blockIdx.x * blockDim.x + threadIdx.x;
    if (idx >= total) return;
    int j = idx & 31;
    int h = (idx >> 5) % nH;
    int m = idx / (32 * nH);
    int t = m & (Tt - 1);
    float c = freq[t * 64 + j * 2 + 0];
    float s = freq[t * 64 + j * 2 + 1];
    float2* p = (float2*)(X + (size_t)m * nH * 64 + h * 64 + j * 2);
    float2 ab = *p;
    float2 o;
    o.x = ab.x * c - ab.y * s;
    o.y = ab.x * s + ab.y * c;
    *p = o;
}

// ---------------------------------------------------------------------------
// Causal flash attention, GQA (kv head = h/4), fp32.  (unchanged, validated)
// ---------------------------------------------------------------------------
#define APAD 68
#define ASM_BYTES (3 * 64 * APAD * 4)

__global__ void __launch_bounds__(256) attn_kernel()
{
    extern __shared__ float smf[];
    float* Qs = smf;
    float* Ks = smf + 64 * APAD;   // reused as P after softmax
    float* Vs = smf + 2 * 64 * APAD;

    const int qt = blockIdx.x;
    const int h  = blockIdx.y;
    const int b  = blockIdx.z;
    const int kvh = h >> 2;

    const int tid = threadIdx.x;
    const int tx  = tid & 15;
    const int ty  = tid >> 4;
    const int r0  = ty * 4;
    const int c0  = tx * 4;

    const size_t qbase = ((size_t)b * Tt + (size_t)qt * 64) * QN + h * Dd;

#pragma unroll
    for (int it = 0; it < 4; it++) {
        int f = tid + it * 256;
        int row = f >> 4, c4 = (f & 15) << 2;
        *(float4*)(&Qs[row * APAD + c4]) =
            *(const float4*)(&g_Q[qbase + (size_t)row * QN + c4]);
    }

    float O[4][4];
    float mrow[4], lrow[4];
#pragma unroll
    for (int i = 0; i < 4; i++) {
        mrow[i] = -1e30f; lrow[i] = 0.0f;
#pragma unroll
        for (int j = 0; j < 4; j++) O[i][j] = 0.0f;
    }

    const float scale = 0.125f;

    for (int kt = 0; kt <= qt; kt++) {
        __syncthreads();
        const size_t kbase = ((size_t)b * Tt + (size_t)kt * 64) * KN + kvh * Dd;
#pragma unroll
        for (int it = 0; it < 4; it++) {
            int f = tid + it * 256;
            int row = f >> 4, c4 = (f & 15) << 2;
            *(float4*)(&Ks[row * APAD + c4]) =
                *(const float4*)(&g_K[kbase + (size_t)row * KN + c4]);
            *(float4*)(&Vs[row * APAD + c4]) =
                *(const float4*)(&g_V[kbase + (size_t)row * KN + c4]);
        }
        __syncthreads();

        float s[4][4];
#pragma unroll
        for (int i = 0; i < 4; i++)
#pragma unroll
            for (int j = 0; j < 4; j++) s[i][j] = 0.0f;

#pragma unroll
        for (int d = 0; d < 64; d += 4) {
            float q[4][4], k[4][4];
#pragma unroll
            for (int i = 0; i < 4; i++)
                *(float4*)(q[i]) = *(const float4*)(&Qs[(r0 + i) * APAD + d]);
#pragma unroll
            for (int j = 0; j < 4; j++)
                *(float4*)(k[j]) = *(const float4*)(&Ks[(c0 + j) * APAD + d]);
#pragma unroll
            for (int i = 0; i < 4; i++)
#pragma unroll
                for (int j = 0; j < 4; j++) {
                    s[i][j] += q[i][0] * k[j][0];
                    s[i][j] += q[i][1] * k[j][1];
                    s[i][j] += q[i][2] * k[j][2];
                    s[i][j] += q[i][3] * k[j][3];
                }
        }

        if (kt == qt) {
#pragma unroll
            for (int i = 0; i < 4; i++) {
                int qg = r0 + i;
#pragma unroll
                for (int j = 0; j < 4; j++) {
                    int kg = c0 + j;
                    s[i][j] = (kg > qg) ? -1e30f : s[i][j] * scale;
                }
            }
        } else {
#pragma unroll
            for (int i = 0; i < 4; i++)
#pragma unroll
                for (int j = 0; j < 4; j++) s[i][j] *= scale;
        }

#pragma unroll
        for (int i = 0; i < 4; i++) {
            float rmax = fmaxf(fmaxf(s[i][0], s[i][1]), fmaxf(s[i][2], s[i][3]));
#pragma unroll
            for (int msk = 8; msk >= 1; msk >>= 1)
                rmax = fmaxf(rmax, __shfl_xor_sync(0xffffffffu, rmax, msk));
            float mn = fmaxf(mrow[i], rmax);
            float alpha = __expf(mrow[i] - mn);
            mrow[i] = mn;
            float rsum = 0.0f;
#pragma unroll
            for (int j = 0; j < 4; j++) {
                float p = __expf(s[i][j] - mn);
                s[i][j] = p;
                rsum += p;
            }
#pragma unroll
            for (int msk = 8; msk >= 1; msk >>= 1)
                rsum += __shfl_xor_sync(0xffffffffu, rsum, msk);
            lrow[i] = lrow[i] * alpha + rsum;
#pragma unroll
            for (int j = 0; j < 4; j++) O[i][j] *= alpha;
        }

        __syncthreads();
#pragma unroll
        for (int i = 0; i < 4; i++)
            *(float4*)(&Ks[(r0 + i) * APAD + c0]) =
                make_float4(s[i][0], s[i][1], s[i][2], s[i][3]);
        __syncthreads();

#pragma unroll
        for (int k = 0; k < 64; k += 4) {
            float p[4][4];
#pragma unroll
            for (int i = 0; i < 4; i++)
                *(float4*)(p[i]) = *(const float4*)(&Ks[(r0 + i) * APAD + k]);
#pragma unroll
            for (int kk = 0; kk < 4; kk++) {
                float4 v = *(const float4*)(&Vs[(k + kk) * APAD + c0]);
#pragma unroll
                for (int i = 0; i < 4; i++) {
                    O[i][0] += p[i][kk] * v.x;
                    O[i][1] += p[i][kk] * v.y;
                    O[i][2] += p[i][kk] * v.z;
                    O[i][3] += p[i][kk] * v.w;
                }
            }
        }
    }

#pragma unroll
    for (int i = 0; i < 4; i++) {
        float inv = 1.0f / lrow[i];
        float4 o = make_float4(O[i][0] * inv, O[i][1] * inv,
                               O[i][2] * inv, O[i][3] * inv);
        *(float4*)(&g_O[qbase + (size_t)(r0 + i) * QN + c0]) = o;
    }
}

// ---------------------------------------------------------------------------
extern "C" void kernel_launch(void* const* d_in, const int* in_sizes, int n_in,
                              void* d_out, int out_size)
{
    const float* x    = (const float*)d_in[0];
    const float* freq = (const float*)d_in[1];
    const float* Wq   = (const float*)d_in[2];
    const float* Wk   = (const float*)d_in[3];
    const float* Wv   = (const float*)d_in[4];
    const float* Wo   = (const float*)d_in[5];
    float* out = (float*)d_out;

    void *pQ, *pK, *pV, *pO;
    cudaGetSymbolAddress(&pQ, g_Q);
    cudaGetSymbolAddress(&pK, g_K);
    cudaGetSymbolAddress(&pV, g_V);
    cudaGetSymbolAddress(&pO, g_O);

    cudaFuncSetAttribute(gemm_tf32_kernel,
                         cudaFuncAttributeMaxDynamicSharedMemorySize,
                         GEMM_SMEM_BYTES);
    cudaFuncSetAttribute(attn_kernel,
                         cudaFuncAttributeMaxDynamicSharedMemorySize, ASM_BYTES);

    // QKV projections (3xTF32 tensor cores)
    gemm_tf32_kernel<<<dim3(QN / BN, Mrows / BM), 256, GEMM_SMEM_BYTES>>>(
        x, Wq, (float*)pQ, Mrows, QN, Ee);
    gemm_tf32_kernel<<<dim3(KN / BN, Mrows / BM), 256, GEMM_SMEM_BYTES>>>(
        x, Wk, (float*)pK, Mrows, KN, Ee);
    gemm_tf32_kernel<<<dim3(KN / BN, Mrows / BM), 256, GEMM_SMEM_BYTES>>>(
        x, Wv, (float*)pV, Mrows, KN, Ee);

    // RoPE
    {
        int totQ = Mrows * Hh * 32;
        rope_kernel<<<(totQ + 255) / 256, 256>>>((float*)pQ, freq, Hh, totQ);
        int totK = Mrows * KVh * 32;
        rope_kernel<<<(totK + 255) / 256, 256>>>((float*)pK, freq, KVh, totK);
    }

    // Attention (fp32 flash, unchanged)
    attn_kernel<<<dim3(Tt / 64, Hh, Bb), 256, ASM_BYTES>>>();

    // Output projection (3xTF32 tensor cores)
    gemm_tf32_kernel<<<dim3(Ee / BN, Mrows / BM), 256, GEMM_SMEM_BYTES>>>(
        (const float*)pO, Wo, out, Mrows, Ee, QN);
}